// round 14
// baseline (speedup 1.0000x reference)
#include <cuda_runtime.h>
#include <stdint.h>

// out[c] = FACTOR * sum_e eng[e] * scales[sp[c], sp[n]]
// R14: scatter grid 592 -> 296 CTAs (2/SM). REDs are fire-and-forget, so LSU
// issue rate (not latency hiding) binds; 16 warps/SM is enough to saturate it,
// and halving the grid halves the 50KB/CTA pack-table staging (30 -> 15 MB L2).
//   pack:    species -> nibble table (u16 stores, 1 int4 load/thread)
//   scatter: tmp[c*16 + sp[n]] += eng[e]      (1 LDS + 1 RED per edge)
//   reduce:  out[c] = FACTOR * dot(scales[sp[c],:], tmp[c,:]); tmp[c,:] = 0
// g_tmp zeroed at module load; reduce re-zeroes bins -> no per-launch zero fill.

#define FACTOR 0.125f  // 1/sqrt(64)

__device__ uint32_t g_packed_species[32768];   // nibble-packed species (<=262144 nodes)
__device__ float    g_tmp[262144 * 16];        // zero at module load; reduce keeps zero

__global__ __launch_bounds__(512) void pack_kernel(
    const int* __restrict__ species, int N, int nhalf)
{
    int i = blockIdx.x * blockDim.x + threadIdx.x;
    if (i >= nhalf) return;
    int base = i << 2;
    uint32_t w = 0;
    if (base + 4 <= N) {
        int4 a = *(const int4*)&species[base];
        w  = ((uint32_t)a.x & 0xFu)
           | (((uint32_t)a.y & 0xFu) << 4)
           | (((uint32_t)a.z & 0xFu) << 8)
           | (((uint32_t)a.w & 0xFu) << 12);
    } else {
        for (int k = 0; k < 4; k++) {
            int idx = base + k;
            if (idx < N) w |= ((uint32_t)species[idx] & 0xFu) << (k << 2);
        }
    }
    ((uint16_t*)g_packed_species)[i] = (uint16_t)w;
}

__global__ __launch_bounds__(512) void edge_scatter_kernel(
    const float* __restrict__ edge_eng,     // [E]
    const int*   __restrict__ ei_center,    // [E]
    const int*   __restrict__ ei_neighbor,  // [E]
    int E, int nwords)
{
    extern __shared__ uint32_t s_pack[];    // nwords words (~50KB)
    for (int i = threadIdx.x; i < nwords; i += blockDim.x)
        s_pack[i] = g_packed_species[i];
    __syncthreads();

    #define SPEC(idx) ((s_pack[(idx) >> 3] >> (((idx) & 7) << 2)) & 0xFu)

    int nvec = E >> 2;
    int tid = blockIdx.x * blockDim.x + threadIdx.x;
    int stride = gridDim.x * blockDim.x;

    const float4* eng4 = (const float4*)edge_eng;
    const int4*   c4   = (const int4*)ei_center;
    const int4*   n4   = (const int4*)ei_neighbor;

    for (int v = tid; v < nvec; v += stride) {
        float4 e = __ldcs(&eng4[v]);
        int4   c = __ldcs(&c4[v]);
        int4   n = __ldcs(&n4[v]);
        atomicAdd(&g_tmp[(c.x << 4) | SPEC(n.x)], e.x);
        atomicAdd(&g_tmp[(c.y << 4) | SPEC(n.y)], e.y);
        atomicAdd(&g_tmp[(c.z << 4) | SPEC(n.z)], e.z);
        atomicAdd(&g_tmp[(c.w << 4) | SPEC(n.w)], e.w);
    }

    int base = nvec << 2;
    for (int i = base + tid; i < E; i += stride) {
        int cc = ei_center[i];
        int nn = ei_neighbor[i];
        atomicAdd(&g_tmp[(cc << 4) | SPEC(nn)], edge_eng[i]);
    }
    #undef SPEC
}

// Reduce + reset. Center species from the 50KB packed table.
__global__ __launch_bounds__(256) void node_reduce_kernel(
    const float* __restrict__ scales,   // [256]
    float* __restrict__ out,            // [N]
    int N)
{
    __shared__ float s_scale[256];
    if (threadIdx.x < 256) s_scale[threadIdx.x] = scales[threadIdx.x];
    __syncthreads();

    int i = blockIdx.x * blockDim.x + threadIdx.x;
    if (i >= N) return;

    int sc = (int)((__ldg(&g_packed_species[i >> 3]) >> ((i & 7) << 2)) & 0xFu);
    const float* srow = &s_scale[sc << 4];
    float4* tp = (float4*)&g_tmp[i << 4];

    float4 t0 = tp[0], t1 = tp[1], t2 = tp[2], t3 = tp[3];
    float acc = 0.0f;
    acc += t0.x * srow[0]  + t0.y * srow[1]  + t0.z * srow[2]  + t0.w * srow[3];
    acc += t1.x * srow[4]  + t1.y * srow[5]  + t1.z * srow[6]  + t1.w * srow[7];
    acc += t2.x * srow[8]  + t2.y * srow[9]  + t2.z * srow[10] + t2.w * srow[11];
    acc += t3.x * srow[12] + t3.y * srow[13] + t3.z * srow[14] + t3.w * srow[15];
    out[i] = acc * FACTOR;

    // Reset bins for the next launch (lines hot in L2 right now).
    float4 z = make_float4(0.f, 0.f, 0.f, 0.f);
    tp[0] = z; tp[1] = z; tp[2] = z; tp[3] = z;
}

extern "C" void kernel_launch(void* const* d_in, const int* in_sizes, int n_in,
                              void* d_out, int out_size) {
    const float* edge_eng = (const float*)d_in[0];  // [E,1]
    const float* scales   = (const float*)d_in[1];  // [16,16]
    const int*   edge_idx = (const int*)d_in[2];    // [2,E]
    const int*   species  = (const int*)d_in[3];    // [N]
    float* out = (float*)d_out;

    int E = in_sizes[0];
    int N = out_size;
    int nwords = (N + 7) >> 3;
    int nhalf  = (N + 3) >> 2;

    const int* ei_center   = edge_idx;
    const int* ei_neighbor = edge_idx + E;

    pack_kernel<<<(nhalf + 511) / 512, 512>>>(species, N, nhalf);

    size_t smem_bytes = (size_t)nwords * sizeof(uint32_t);
    cudaFuncSetAttribute(edge_scatter_kernel,
                         cudaFuncAttributeMaxDynamicSharedMemorySize,
                         (int)smem_bytes);

    int threads = 512;
    int blocks = 148 * 2;   // 2 CTAs/SM: halves pack-table staging vs 4/SM
    int nvec = E >> 2;
    int need = (nvec + threads - 1) / threads;
    if (blocks > need) blocks = need > 0 ? need : 1;
    edge_scatter_kernel<<<blocks, threads, smem_bytes>>>(
        edge_eng, ei_center, ei_neighbor, E, nwords);

    node_reduce_kernel<<<(N + 255) / 256, 256>>>(scales, out, N);
}

// round 15
// speedup vs baseline: 1.0820x; 1.0820x over previous
#include <cuda_runtime.h>
#include <stdint.h>

// out[c] = FACTOR * sum_e eng[e] * scales[sp[c], sp[n]]
// R15: scatter = 1024 thr x 296 CTAs -> same 32 warps/SM as the 52.1us best,
// but half the CTAs => pack-table staging 30 -> 15 MB and half the staging
// barriers. (R14's 296x512 halved warps/SM and regressed; warp count is the
// LSU feed for the RED-dominated MIO pipe.)
//   pack:    species -> nibble table (u16 stores, 1 int4 load/thread)
//   scatter: tmp[c*16 + sp[n]] += eng[e]      (1 LDS + 1 RED per edge)
//   reduce:  out[c] = FACTOR * dot(scales[sp[c],:], tmp[c,:]); tmp[c,:] = 0
// g_tmp zeroed at module load; reduce re-zeroes bins -> no per-launch zero fill.

#define FACTOR 0.125f  // 1/sqrt(64)

__device__ uint32_t g_packed_species[32768];   // nibble-packed species (<=262144 nodes)
__device__ float    g_tmp[262144 * 16];        // zero at module load; reduce keeps zero

__global__ __launch_bounds__(256) void pack_kernel(
    const int* __restrict__ species, int N, int nhalf)
{
    int i = blockIdx.x * blockDim.x + threadIdx.x;
    if (i >= nhalf) return;
    int base = i << 2;
    uint32_t w = 0;
    if (base + 4 <= N) {
        int4 a = *(const int4*)&species[base];
        w  = ((uint32_t)a.x & 0xFu)
           | (((uint32_t)a.y & 0xFu) << 4)
           | (((uint32_t)a.z & 0xFu) << 8)
           | (((uint32_t)a.w & 0xFu) << 12);
    } else {
        for (int k = 0; k < 4; k++) {
            int idx = base + k;
            if (idx < N) w |= ((uint32_t)species[idx] & 0xFu) << (k << 2);
        }
    }
    ((uint16_t*)g_packed_species)[i] = (uint16_t)w;
}

__global__ __launch_bounds__(1024, 2) void edge_scatter_kernel(
    const float* __restrict__ edge_eng,     // [E]
    const int*   __restrict__ ei_center,    // [E]
    const int*   __restrict__ ei_neighbor,  // [E]
    int E, int nwords)
{
    extern __shared__ uint32_t s_pack[];    // nwords words (~50KB)
    for (int i = threadIdx.x; i < nwords; i += blockDim.x)
        s_pack[i] = g_packed_species[i];
    __syncthreads();

    #define SPEC(idx) ((s_pack[(idx) >> 3] >> (((idx) & 7) << 2)) & 0xFu)

    int nvec = E >> 2;
    int tid = blockIdx.x * blockDim.x + threadIdx.x;
    int stride = gridDim.x * blockDim.x;

    const float4* eng4 = (const float4*)edge_eng;
    const int4*   c4   = (const int4*)ei_center;
    const int4*   n4   = (const int4*)ei_neighbor;

    for (int v = tid; v < nvec; v += stride) {
        float4 e = __ldcs(&eng4[v]);
        int4   c = __ldcs(&c4[v]);
        int4   n = __ldcs(&n4[v]);
        atomicAdd(&g_tmp[(c.x << 4) | SPEC(n.x)], e.x);
        atomicAdd(&g_tmp[(c.y << 4) | SPEC(n.y)], e.y);
        atomicAdd(&g_tmp[(c.z << 4) | SPEC(n.z)], e.z);
        atomicAdd(&g_tmp[(c.w << 4) | SPEC(n.w)], e.w);
    }

    int base = nvec << 2;
    for (int i = base + tid; i < E; i += stride) {
        int cc = ei_center[i];
        int nn = ei_neighbor[i];
        atomicAdd(&g_tmp[(cc << 4) | SPEC(nn)], edge_eng[i]);
    }
    #undef SPEC
}

// Reduce + reset. Center species from the 50KB packed table.
__global__ __launch_bounds__(256) void node_reduce_kernel(
    const float* __restrict__ scales,   // [256]
    float* __restrict__ out,            // [N]
    int N)
{
    __shared__ float s_scale[256];
    if (threadIdx.x < 256) s_scale[threadIdx.x] = scales[threadIdx.x];
    __syncthreads();

    int i = blockIdx.x * blockDim.x + threadIdx.x;
    if (i >= N) return;

    int sc = (int)((__ldg(&g_packed_species[i >> 3]) >> ((i & 7) << 2)) & 0xFu);
    const float* srow = &s_scale[sc << 4];
    float4* tp = (float4*)&g_tmp[i << 4];

    float4 t0 = tp[0], t1 = tp[1], t2 = tp[2], t3 = tp[3];
    float acc = 0.0f;
    acc += t0.x * srow[0]  + t0.y * srow[1]  + t0.z * srow[2]  + t0.w * srow[3];
    acc += t1.x * srow[4]  + t1.y * srow[5]  + t1.z * srow[6]  + t1.w * srow[7];
    acc += t2.x * srow[8]  + t2.y * srow[9]  + t2.z * srow[10] + t2.w * srow[11];
    acc += t3.x * srow[12] + t3.y * srow[13] + t3.z * srow[14] + t3.w * srow[15];
    out[i] = acc * FACTOR;

    // Reset bins for the next launch (lines hot in L2 right now).
    float4 z = make_float4(0.f, 0.f, 0.f, 0.f);
    tp[0] = z; tp[1] = z; tp[2] = z; tp[3] = z;
}

extern "C" void kernel_launch(void* const* d_in, const int* in_sizes, int n_in,
                              void* d_out, int out_size) {
    const float* edge_eng = (const float*)d_in[0];  // [E,1]
    const float* scales   = (const float*)d_in[1];  // [16,16]
    const int*   edge_idx = (const int*)d_in[2];    // [2,E]
    const int*   species  = (const int*)d_in[3];    // [N]
    float* out = (float*)d_out;

    int E = in_sizes[0];
    int N = out_size;
    int nwords = (N + 7) >> 3;
    int nhalf  = (N + 3) >> 2;

    const int* ei_center   = edge_idx;
    const int* ei_neighbor = edge_idx + E;

    pack_kernel<<<(nhalf + 255) / 256, 256>>>(species, N, nhalf);

    size_t smem_bytes = (size_t)nwords * sizeof(uint32_t);
    cudaFuncSetAttribute(edge_scatter_kernel,
                         cudaFuncAttributeMaxDynamicSharedMemorySize,
                         (int)smem_bytes);

    int threads = 1024;
    int blocks = 148 * 2;   // 32 warps/SM (matches 52.1us best), half the staging
    int nvec = E >> 2;
    int need = (nvec + threads - 1) / threads;
    if (blocks > need) blocks = need > 0 ? need : 1;
    edge_scatter_kernel<<<blocks, threads, smem_bytes>>>(
        edge_eng, ei_center, ei_neighbor, E, nwords);

    node_reduce_kernel<<<(N + 255) / 256, 256>>>(scales, out, N);
}